// round 9
// baseline (speedup 1.0000x reference)
#include <cuda_runtime.h>
#include <cstdint>

#define N_NODES 100000
#define N_EDGES 1600000
#define NCHUNK 196       // 196*512 >= N_NODES (scan chunks of 512)
#define NBG 592          // 4 blocks/SM x 148 SMs -> co-resident, barrier-safe
#define NTG 256

// ---------------- scratch (device globals; no allocation allowed) ----------
__device__ float g_y[N_NODES * 32];     // x @ W1_l
__device__ float g_z[N_NODES * 32];     // x @ W1_r
__device__ float g_h1[N_NODES * 32];
__device__ int2  g_edge[N_EDGES];       // packed (src, dst)
__device__ int   g_csr[N_EDGES];        // src ids grouped by dst
__device__ int   g_off[N_NODES + 1];    // counts -> exclusive offsets
__device__ int   g_part[N_NODES + 512]; // scan partials
__device__ int   g_cur[N_NODES];        // bucket cursors
__device__ int   g_bsum[256];
__device__ int   g_is64;
__device__ unsigned g_arrive;
__device__ unsigned g_release;

// ---------------- JAX threefry2x32 (partitionable scheme) ------------------
struct TF2 { uint32_t a, b; };

__host__ __device__ constexpr uint32_t rotl32(uint32_t v, int r) {
    return (v << r) | (v >> (32 - r));
}

__host__ __device__ constexpr TF2 threefry(uint32_t k0, uint32_t k1,
                                           uint32_t x0, uint32_t x1) {
    const uint32_t ks0 = k0, ks1 = k1, ks2 = k0 ^ k1 ^ 0x1BD11BDAu;
    const int ra[4] = {13, 15, 26, 6};
    const int rb[4] = {17, 29, 16, 24};
    x0 += ks0; x1 += ks1;
#pragma unroll
    for (int i = 0; i < 4; i++) { x0 += x1; x1 = rotl32(x1, ra[i]); x1 ^= x0; }
    x0 += ks1; x1 += ks2 + 1u;
#pragma unroll
    for (int i = 0; i < 4; i++) { x0 += x1; x1 = rotl32(x1, rb[i]); x1 ^= x0; }
    x0 += ks2; x1 += ks0 + 2u;
#pragma unroll
    for (int i = 0; i < 4; i++) { x0 += x1; x1 = rotl32(x1, ra[i]); x1 ^= x0; }
    x0 += ks0; x1 += ks1 + 3u;
#pragma unroll
    for (int i = 0; i < 4; i++) { x0 += x1; x1 = rotl32(x1, rb[i]); x1 ^= x0; }
    x0 += ks1; x1 += ks2 + 4u;
#pragma unroll
    for (int i = 0; i < 4; i++) { x0 += x1; x1 = rotl32(x1, ra[i]); x1 ^= x0; }
    x0 += ks2; x1 += ks0 + 5u;
    return {x0, x1};
}

constexpr TF2 DK0 = threefry(0u, 42u, 0u, 0u);
constexpr TF2 DK1 = threefry(0u, 42u, 0u, 1u);

template <uint32_t K0, uint32_t K1>
__device__ __forceinline__ bool drop_bit(uint32_t j) {
    TF2 r = threefry(K0, K1, 0u, j);
    return ((r.a ^ r.b) >> 31) != 0;   // MSB set -> u >= 0.5 -> dropped
}

// ---------------- packed f32x2 helpers (sm_103a) ---------------------------
__device__ __forceinline__ unsigned long long pk2(float x, float y) {
    unsigned long long r;
    asm("mov.b64 %0, {%1, %2};" : "=l"(r) : "f"(x), "f"(y));
    return r;
}
__device__ __forceinline__ unsigned long long fma2(unsigned long long a,
                                                   unsigned long long b,
                                                   unsigned long long c) {
    unsigned long long d;
    asm("fma.rn.f32x2 %0, %1, %2, %3;" : "=l"(d) : "l"(a), "l"(b), "l"(c));
    return d;
}
__device__ __forceinline__ void upk2(unsigned long long v, float& x, float& y) {
    asm("mov.b64 {%0, %1}, %2;" : "=f"(x), "=f"(y) : "l"(v));
}

// ---------------- k_pre: dense pre-GEMM + all per-replay resets -------------
// y = x @ W1_l, z = x @ W1_r; 4 nodes/warp, packed weights, packed FMA.
// Also zeroes g_off histogram, resets barrier counters, detects edge dtype.
__global__ void __launch_bounds__(256) k_pre(const float* __restrict__ x,
                      const float* __restrict__ Wl,
                      const float* __restrict__ Wr,
                      const uint32_t* __restrict__ ei) {
    __shared__ float2 swlr[64 * 32];      // (Wl, Wr) pairs, 16KB
    __shared__ float  rows[8][4][64];     // 8KB
    int tid = threadIdx.x;
    for (int i = tid; i < 2048; i += 256) swlr[i] = make_float2(Wl[i], Wr[i]);
    int gt = blockIdx.x * 256 + tid;
    if (gt <= N_NODES) g_off[gt] = 0;
    if (blockIdx.x == 0 && tid == 0) {
        g_arrive = 0u;
        g_release = 0u;
        int is64 = 1;
        for (int k = 0; k < 64; k++)
            if (ei[2 * k + 1] != 0u) { is64 = 0; break; }
        g_is64 = is64;
    }
    int w = tid >> 5, lane = tid & 31;
    int nb = blockIdx.x * 32 + w * 4;     // grid = 3125 exact
#pragma unroll
    for (int n = 0; n < 4; n++) {
        rows[w][n][lane]      = x[(nb + n) * 64 + lane];
        rows[w][n][32 + lane] = x[(nb + n) * 64 + 32 + lane];
    }
    __syncthreads();
    unsigned long long acc[4];
#pragma unroll
    for (int n = 0; n < 4; n++) acc[n] = pk2(0.f, 0.f);
#pragma unroll
    for (int k = 0; k < 64; k++) {
        float2 wv = swlr[k * 32 + lane];
        unsigned long long wp = pk2(wv.x, wv.y);
#pragma unroll
        for (int n = 0; n < 4; n++) {
            float xv = rows[w][n][k];
            acc[n] = fma2(pk2(xv, xv), wp, acc[n]);
        }
    }
#pragma unroll
    for (int n = 0; n < 4; n++) {
        float yl, yr;
        upk2(acc[n], yl, yr);
        g_y[(nb + n) * 32 + lane] = yl;
        g_z[(nb + n) * 32 + lane] = yr;
    }
}

// ---------------- k_graph: full CSR build in ONE launch ----------------------
// 592 blocks x 256 (exactly 4 CTAs/SM, ~1KB smem, low regs) -> all co-resident,
// so the software grid barrier is deadlock-free.
// Phases: histogram -> B -> chunk scan -> B -> apply offsets -> B -> bucket.
__global__ void __launch_bounds__(NTG, 4) k_graph(const uint32_t* __restrict__ ei) {
    __shared__ int sh[NTG];
    const int tid = threadIdx.x;
    const int bid = blockIdx.x;
    unsigned target = 0;

    auto GBAR = [&]() {
        __syncthreads();
        __threadfence();
        target += 1;
        if (tid == 0) {
            unsigned a = atomicAdd(&g_arrive, 1u) + 1u;
            if (a == target * NBG) {
                *((volatile unsigned*)&g_release) = target;
            } else {
                while (*((volatile unsigned*)&g_release) < target) __nanosleep(64);
            }
        }
        __syncthreads();
    };

    // ---- phase 1: pack edges + dst histogram ----
    {
        int is64 = g_is64;
        for (int e = bid * NTG + tid; e < N_EDGES; e += NBG * NTG) {
            int s, d;
            if (is64) {
                uint2 sv = reinterpret_cast<const uint2*>(ei)[e];
                uint2 dv = reinterpret_cast<const uint2*>(ei)[N_EDGES + e];
                s = (int)sv.x; d = (int)dv.x;
            } else {
                s = (int)ei[e];
                d = (int)ei[N_EDGES + e];
            }
            g_edge[e] = make_int2(s, d);
            atomicAdd(&g_off[d], 1);
        }
    }
    GBAR();   // 1

    // ---- phase 2: per-chunk exclusive scan (512 counts/chunk, 2/thread) ----
    if (bid < NCHUNK) {
        int i0 = bid * 512 + tid * 2;
        int v0 = (i0     < N_NODES) ? __ldcg(&g_off[i0])     : 0;
        int v1 = (i0 + 1 < N_NODES) ? __ldcg(&g_off[i0 + 1]) : 0;
        int s2 = v0 + v1;
        sh[tid] = s2;
        __syncthreads();
        for (int o = 1; o < NTG; o <<= 1) {
            int t = (tid >= o) ? sh[tid - o] : 0;
            __syncthreads();
            sh[tid] += t;
            __syncthreads();
        }
        int ex = sh[tid] - s2;
        if (i0     < N_NODES) g_part[i0]     = ex;
        if (i0 + 1 < N_NODES) g_part[i0 + 1] = ex + v0;
        if (tid == NTG - 1) g_bsum[bid] = sh[NTG - 1];
    }
    GBAR();   // 2

    // ---- phase 3: apply (reduce preceding chunk totals, write offs+cursors) --
    if (bid < NCHUNK) {
        int v = (tid < bid) ? __ldcg(&g_bsum[tid]) : 0;   // bid <= 195 < 256
        sh[tid] = v;
        __syncthreads();
        for (int o = NTG / 2; o > 0; o >>= 1) {
            if (tid < o) sh[tid] += sh[tid + o];
            __syncthreads();
        }
        int base = sh[0];
        for (int idx = tid; idx < 512; idx += NTG) {
            int i = bid * 512 + idx;
            if (i < N_NODES) {
                int o = g_part[i] + base;   // own block's g_part -> L1-coherent
                g_off[i] = o;
                g_cur[i] = o;
            }
        }
        if (bid == 0 && tid == 0) g_off[N_NODES] = N_EDGES;
    }
    GBAR();   // 3

    // ---- phase 4: bucket scatter (CSR fill); reads own-written g_edge range --
    for (int e = bid * NTG + tid; e < N_EDGES; e += NBG * NTG) {
        int2 p = g_edge[e];
        int pos = atomicAdd(&g_cur[p.y], 1);
        g_csr[pos] = p.x;
    }
}

// ---------------- aggregation kernels (R7 gather, proven) --------------------
// layer 1: warp per node; gather-sum y rows, fuse bias+z+lrelu+dropout
__global__ void k_agg1(const float* __restrict__ b) {
    int w = threadIdx.x >> 5, lane = threadIdx.x & 31;
    int node = blockIdx.x * 8 + w;                    // grid = 12500 exact
    int beg = g_off[node], end = g_off[node + 1];
    float acc = 0.f;
    int j = beg;
    for (; j + 4 <= end; j += 4) {
        int s0 = __ldg(g_csr + j),     s1 = __ldg(g_csr + j + 1);
        int s2 = __ldg(g_csr + j + 2), s3 = __ldg(g_csr + j + 3);
        float v0 = __ldg(g_y + s0 * 32 + lane);
        float v1 = __ldg(g_y + s1 * 32 + lane);
        float v2 = __ldg(g_y + s2 * 32 + lane);
        float v3 = __ldg(g_y + s3 * 32 + lane);
        acc += (v0 + v1) + (v2 + v3);
    }
    for (; j < end; j++)
        acc += __ldg(g_y + __ldg(g_csr + j) * 32 + lane);
    float inv = 1.0f / fmaxf((float)(end - beg), 1.0f);
    float v = fmaf(acc, inv, b[lane] + g_z[node * 32 + lane]);
    v = v > 0.f ? v : 0.01f * v;
    uint32_t jj = (uint32_t)(node * 32 + lane);
    g_h1[jj] = drop_bit<DK0.a, DK0.b>(jj) ? 0.f : 2.0f * v;
}

// layer 2 fused: gather-mean, GEMMs (4 nodes/warp, packed weights),
// dropout, l2norm
__global__ void __launch_bounds__(256) k_agg2(const float* __restrict__ Wl,
                       const float* __restrict__ b,
                       const float* __restrict__ Wr,
                       float* __restrict__ out) {
    __shared__ float2 swl2[32 * 32], swr2[32 * 32];   // 8KB + 8KB
    __shared__ float  rows[8][4][64];                 // 8KB
    int tid = threadIdx.x;
    for (int i = tid; i < 1024; i += 256) {
        int k = i >> 5, c = i & 31;
        swl2[i] = make_float2(Wl[k * 64 + c], Wl[k * 64 + 32 + c]);
        swr2[i] = make_float2(Wr[k * 64 + c], Wr[k * 64 + 32 + c]);
    }
    __syncthreads();
    int w = tid >> 5, lane = tid & 31;
    int nb = blockIdx.x * 32 + w * 4;                 // grid = 3125 exact
#pragma unroll
    for (int n = 0; n < 4; n++) {
        int node = nb + n;
        int beg = g_off[node], end = g_off[node + 1];
        float acc = 0.f;
        int j = beg;
        for (; j + 4 <= end; j += 4) {
            int s0 = __ldg(g_csr + j),     s1 = __ldg(g_csr + j + 1);
            int s2 = __ldg(g_csr + j + 2), s3 = __ldg(g_csr + j + 3);
            float v0 = __ldg(g_h1 + s0 * 32 + lane);
            float v1 = __ldg(g_h1 + s1 * 32 + lane);
            float v2 = __ldg(g_h1 + s2 * 32 + lane);
            float v3 = __ldg(g_h1 + s3 * 32 + lane);
            acc += (v0 + v1) + (v2 + v3);
        }
        for (; j < end; j++)
            acc += __ldg(g_h1 + __ldg(g_csr + j) * 32 + lane);
        float inv = 1.0f / fmaxf((float)(end - beg), 1.0f);
        rows[w][n][lane]      = acc * inv;
        rows[w][n][32 + lane] = g_h1[node * 32 + lane];
    }
    __syncwarp();
    float bb0 = b[lane], bb1 = b[32 + lane];
    float a0[4], a1[4];
#pragma unroll
    for (int n = 0; n < 4; n++) { a0[n] = bb0; a1[n] = bb1; }
#pragma unroll
    for (int k = 0; k < 32; k++) {
        float2 wl = swl2[k * 32 + lane];
        float2 wr = swr2[k * 32 + lane];
#pragma unroll
        for (int n = 0; n < 4; n++) {
            float m = rows[w][n][k];
            float h = rows[w][n][32 + k];
            a0[n] = fmaf(m, wl.x, fmaf(h, wr.x, a0[n]));
            a1[n] = fmaf(m, wl.y, fmaf(h, wr.y, a1[n]));
        }
    }
#pragma unroll
    for (int n = 0; n < 4; n++) {
        int node = nb + n;
        uint32_t j0 = (uint32_t)(node * 64 + lane);
        float v0 = drop_bit<DK1.a, DK1.b>(j0)       ? 0.f : 2.0f * a0[n];
        float v1 = drop_bit<DK1.a, DK1.b>(j0 + 32u) ? 0.f : 2.0f * a1[n];
        float ss = v0 * v0 + v1 * v1;
#pragma unroll
        for (int o = 16; o > 0; o >>= 1)
            ss += __shfl_xor_sync(0xffffffffu, ss, o);
        float scale = 1.0f / fmaxf(sqrtf(ss), 1e-12f);
        out[node * 64 + lane]      = v0 * scale;
        out[node * 64 + 32 + lane] = v1 * scale;
    }
}

// ---------------- launch -----------------------------------------------------
extern "C" void kernel_launch(void* const* d_in, const int* in_sizes, int n_in,
                              void* d_out, int out_size) {
    const float*    x   = (const float*)d_in[0];
    const uint32_t* ei  = (const uint32_t*)d_in[1];   // int32 or int64 (detected)
    const float*    W1l = (const float*)d_in[2];
    const float*    b1  = (const float*)d_in[3];
    const float*    W1r = (const float*)d_in[4];
    const float*    W2l = (const float*)d_in[5];
    const float*    b2  = (const float*)d_in[6];
    const float*    W2r = (const float*)d_in[7];
    float* out = (float*)d_out;

    k_pre<<<N_NODES / 32, 256>>>(x, W1l, W1r, ei);     // 3125 blocks
    k_graph<<<NBG, NTG>>>(ei);                         // 592 blocks, 3 grid bars
    k_agg1<<<N_NODES / 8, 256>>>(b1);                  // 12500 blocks
    k_agg2<<<N_NODES / 32, 256>>>(W2l, b2, W2r, out);  // 3125 blocks
}